// round 4
// baseline (speedup 1.0000x reference)
#include <cuda_runtime.h>
#include <math.h>

#define H 256
#define H2 512
#define VOCAB 8192
#define SEQ 4096

// ---------------- device scratch (no allocations allowed) ----------------
__device__ float g_wah[H];           // Wa@h + Wa_b + Ua_b
__device__ float g_Eij[2 * SEQ];     // attention scores, partial over two n-halves
__device__ float g_CiP[16][H2];      // Ci partials (deterministic reduction)
__device__ float g_Ci[H2];           // context vector
__device__ float g_pre[3 * H];       // gate pre-activations: z, r, h-partial
__device__ float g_logits[VOCAB];

// ---------------- f32x2 packed-math helpers (sm_100+) ----------------
static __device__ __forceinline__ unsigned long long pack2(float lo, float hi) {
    unsigned long long r;
    asm("mov.b64 %0, {%1,%2};" : "=l"(r) : "f"(lo), "f"(hi));
    return r;
}
static __device__ __forceinline__ void unpack2(unsigned long long v, float& lo, float& hi) {
    asm("mov.b64 {%0,%1}, %2;" : "=f"(lo), "=f"(hi) : "l"(v));
}
static __device__ __forceinline__ void fma2(unsigned long long& d,
                                            unsigned long long a,
                                            unsigned long long b) {
    asm("fma.rn.f32x2 %0, %1, %2, %0;" : "+l"(d) : "l"(a), "l"(b));
}

// ---------------- K1: wa_h[n] = Wa@hidden + Wa_b + Ua_b ----------------
__global__ void k1_wah(const float* __restrict__ Wa_w, const float* __restrict__ Wa_b,
                       const float* __restrict__ Ua_b, const float* __restrict__ hidden) {
    int w = threadIdx.x >> 5, lane = threadIdx.x & 31;
    int row = blockIdx.x * 8 + w;
    float s = 0.f;
    for (int k = lane; k < H; k += 32) s += Wa_w[row * H + k] * hidden[k];
    for (int o = 16; o; o >>= 1) s += __shfl_xor_sync(0xffffffffu, s, o);
    if (lane == 0) g_wah[row] = s + Wa_b[row] + Ua_b[row];
}

// ---------------- K2: fused attention-score GEMM ----------------
// C[s,n] = enc[s,:] . Ua_w[n,:];  Eij_part[by][s] = sum_n Va[n]*tanh(C+wa_h[n])
#define TM 64
#define TN 128
#define KT 32

__global__ __launch_bounds__(256) void k2_attn(const float* __restrict__ enc,
                                               const float* __restrict__ Ua_w,
                                               const float* __restrict__ Va_w) {
    __shared__ __align__(16) unsigned long long As2[TM][KT + 1]; // (a,a) packed
    __shared__ __align__(16) float Bs[KT][TN];
    __shared__ float wah_s[TN];
    __shared__ float vas[TN];

    int tid = threadIdx.x;
    int s0 = blockIdx.x * TM;
    int n0 = blockIdx.y * TN;
    if (tid < TN) { wah_s[tid] = g_wah[n0 + tid]; vas[tid] = Va_w[n0 + tid]; }

    int tidx = tid & 15;   // n-group (16)
    int tidy = tid >> 4;   // m-group (16)

    unsigned long long acc[4][4];
#pragma unroll
    for (int i = 0; i < 4; i++)
#pragma unroll
        for (int j = 0; j < 4; j++) acc[i][j] = 0ull;

    int ar = tid >> 2, aq = tid & 3;   // A loader: row 0..63, quad 0..3
    int bn = tid >> 1, bh = tid & 1;   // B loader: row 0..127, half 0..1
    const float4* Abase = reinterpret_cast<const float4*>(enc + (size_t)(s0 + ar) * H2);
    const float4* Bbase = reinterpret_cast<const float4*>(Ua_w + (size_t)(n0 + bn) * H2);

    float4 a0 = Abase[aq], a1 = Abase[aq + 4];
    float4 b0 = Bbase[bh * 4 + 0], b1 = Bbase[bh * 4 + 1];
    float4 b2 = Bbase[bh * 4 + 2], b3 = Bbase[bh * 4 + 3];

    const int NIT = H2 / KT;
    for (int it = 0; it < NIT; ++it) {
        // stage registers -> smem
        As2[ar][4 * aq + 0]  = pack2(a0.x, a0.x);
        As2[ar][4 * aq + 1]  = pack2(a0.y, a0.y);
        As2[ar][4 * aq + 2]  = pack2(a0.z, a0.z);
        As2[ar][4 * aq + 3]  = pack2(a0.w, a0.w);
        As2[ar][4 * aq + 16] = pack2(a1.x, a1.x);
        As2[ar][4 * aq + 17] = pack2(a1.y, a1.y);
        As2[ar][4 * aq + 18] = pack2(a1.z, a1.z);
        As2[ar][4 * aq + 19] = pack2(a1.w, a1.w);
        int cb = bh * 16;
        Bs[cb + 0][bn] = b0.x;  Bs[cb + 1][bn] = b0.y;
        Bs[cb + 2][bn] = b0.z;  Bs[cb + 3][bn] = b0.w;
        Bs[cb + 4][bn] = b1.x;  Bs[cb + 5][bn] = b1.y;
        Bs[cb + 6][bn] = b1.z;  Bs[cb + 7][bn] = b1.w;
        Bs[cb + 8][bn] = b2.x;  Bs[cb + 9][bn] = b2.y;
        Bs[cb + 10][bn] = b2.z; Bs[cb + 11][bn] = b2.w;
        Bs[cb + 12][bn] = b3.x; Bs[cb + 13][bn] = b3.y;
        Bs[cb + 14][bn] = b3.z; Bs[cb + 15][bn] = b3.w;
        __syncthreads();

        if (it + 1 < NIT) {  // prefetch next tile (hides GMEM latency behind FMAs)
            int o = (it + 1) * 8;
            a0 = Abase[o + aq];          a1 = Abase[o + aq + 4];
            b0 = Bbase[o + bh * 4 + 0];  b1 = Bbase[o + bh * 4 + 1];
            b2 = Bbase[o + bh * 4 + 2];  b3 = Bbase[o + bh * 4 + 3];
        }

#pragma unroll 8
        for (int k = 0; k < KT; k++) {
            unsigned long long a[4], b[4];
#pragma unroll
            for (int i = 0; i < 4; i++) a[i] = As2[tidy * 4 + i][k];
#pragma unroll
            for (int j = 0; j < 4; j++)
                b[j] = *reinterpret_cast<const unsigned long long*>(&Bs[k][tidx * 2 + 32 * j]);
#pragma unroll
            for (int i = 0; i < 4; i++)
#pragma unroll
                for (int j = 0; j < 4; j++) fma2(acc[i][j], a[i], b[j]);
        }
        __syncthreads();
    }

    // fused epilogue: tanh + Va-dot, reduce across the 16 n-thread groups
#pragma unroll
    for (int i = 0; i < 4; i++) {
        float p = 0.f;
#pragma unroll
        for (int j = 0; j < 4; j++) {
            float c0, c1;
            unpack2(acc[i][j], c0, c1);
            int nl = tidx * 2 + 32 * j;
            float e0 = tanhf(c0 + wah_s[nl]);
            float e1 = tanhf(c1 + wah_s[nl + 1]);
            p += e0 * vas[nl] + e1 * vas[nl + 1];
        }
        for (int o = 1; o < 16; o <<= 1) p += __shfl_xor_sync(0xffffffffu, p, o, 16);
        if (tidx == 0) g_Eij[blockIdx.y * SEQ + s0 + tidy * 4 + i] = p;
    }
}

// ---------------- K3: softmax over S (single block) ----------------------
__global__ __launch_bounds__(256) void k3_softmax(float* __restrict__ aij) {
    __shared__ float red[8];
    __shared__ float stat;
    int tid = threadIdx.x;

    float e[16];
    float mx = -1e30f;
#pragma unroll
    for (int i = 0; i < 16; i++) {
        e[i] = g_Eij[i * 256 + tid] + g_Eij[SEQ + i * 256 + tid];
        mx = fmaxf(mx, e[i]);
    }
    for (int o = 16; o; o >>= 1) mx = fmaxf(mx, __shfl_xor_sync(0xffffffffu, mx, o));
    if ((tid & 31) == 0) red[tid >> 5] = mx;
    __syncthreads();
    if (tid == 0) {
        float m = red[0];
        for (int i = 1; i < 8; i++) m = fmaxf(m, red[i]);
        stat = m;
    }
    __syncthreads();
    mx = stat;

    float sum = 0.f;
#pragma unroll
    for (int i = 0; i < 16; i++) { e[i] = expf(e[i] - mx); sum += e[i]; }
    for (int o = 16; o; o >>= 1) sum += __shfl_xor_sync(0xffffffffu, sum, o);
    __syncthreads();
    if ((tid & 31) == 0) red[tid >> 5] = sum;
    __syncthreads();
    if (tid == 0) {
        float t = 0.f;
        for (int i = 0; i < 8; i++) t += red[i];
        stat = t;
    }
    __syncthreads();
    float inv = 1.f / stat;
#pragma unroll
    for (int i = 0; i < 16; i++) aij[i * 256 + tid] = e[i] * inv;
}

// ---------------- K4: Ci partials (16 blocks, deterministic) --------------
__global__ __launch_bounds__(256) void k4_ci(const float* __restrict__ enc,
                                             const float* __restrict__ aij) {
    int b = blockIdx.x, tid = threadIdx.x;
    float a0 = 0.f, a1 = 0.f;
    const float* ep = enc + (size_t)b * 256 * H2;
    const float* ap = aij + b * 256;
    for (int s = 0; s < 256; s++) {
        float w = __ldg(ap + s);
        a0 += w * ep[(size_t)s * H2 + tid];
        a1 += w * ep[(size_t)s * H2 + tid + 256];
    }
    g_CiP[b][tid] = a0;
    g_CiP[b][tid + 256] = a1;
}

// ---------------- K5: reduce Ci partials (fixed order) --------------------
__global__ __launch_bounds__(512) void k5_cired() {
    int tid = threadIdx.x;
    float s = 0.f;
#pragma unroll
    for (int b = 0; b < 16; b++) s += g_CiP[b][tid];
    g_Ci[tid] = s;
}

// ---------------- K6: gate pre-activations (768 blocks, block-per-row) ---
__global__ __launch_bounds__(256) void k6_gates(
    const float* __restrict__ emb, const int* __restrict__ tokp,
    const float* __restrict__ hidden,
    const float* __restrict__ Uz, const float* __restrict__ Uzb,
    const float* __restrict__ Wz, const float* __restrict__ Wzb,
    const float* __restrict__ Cz, const float* __restrict__ Czb,
    const float* __restrict__ Ur, const float* __restrict__ Urb,
    const float* __restrict__ Wr, const float* __restrict__ Wrb,
    const float* __restrict__ Cr, const float* __restrict__ Crb,
    const float* __restrict__ Uh, const float* __restrict__ Uhb,
    const float* __restrict__ Whb,
    const float* __restrict__ Ch, const float* __restrict__ Chb) {
    __shared__ float red[8];
    int g = blockIdx.x >> 8, row = blockIdx.x & 255, tid = threadIdx.x;
    const float* U = (g == 0) ? Uz : (g == 1) ? Ur : Uh;
    int tok = __ldg(tokp);
    const float4* y4 = reinterpret_cast<const float4*>(emb + (size_t)tok * VOCAB);
    const float4* u4 = reinterpret_cast<const float4*>(U + (size_t)row * VOCAB);

    float s = 0.f;
#pragma unroll 4
    for (int i = tid; i < VOCAB / 4; i += 256) {
        float4 u = u4[i], y = y4[i];
        s += u.x * y.x + u.y * y.y + u.z * y.z + u.w * y.w;
    }
    if (g < 2) {
        const float* W = (g == 0) ? Wz : Wr;
        s += W[row * H + tid] * hidden[tid];
    }
    const float* C = (g == 0) ? Cz : (g == 1) ? Cr : Ch;
    s += C[row * H2 + tid] * g_Ci[tid] + C[row * H2 + tid + 256] * g_Ci[tid + 256];

    for (int o = 16; o; o >>= 1) s += __shfl_xor_sync(0xffffffffu, s, o);
    if ((tid & 31) == 0) red[tid >> 5] = s;
    __syncthreads();
    if (tid == 0) {
        float t = 0.f;
        for (int i = 0; i < 8; i++) t += red[i];
        float bias = (g == 0) ? (Uzb[row] + Wzb[row] + Czb[row])
                   : (g == 1) ? (Urb[row] + Wrb[row] + Crb[row])
                              : (Uhb[row] + Whb[row] + Chb[row]);
        g_pre[g * H + row] = t + bias;
    }
}

// ---------------- K7: finish GRU -> hidden_new (32 blocks) ----------------
__global__ __launch_bounds__(256) void k7_combine(const float* __restrict__ Wh,
                                                  const float* __restrict__ hidden,
                                                  float* __restrict__ hn_out) {
    __shared__ float rh[H];
    int tid = threadIdx.x;
    float rr = 1.f / (1.f + expf(-g_pre[H + tid]));
    rh[tid] = rr * hidden[tid];
    __syncthreads();
    int w = tid >> 5, lane = tid & 31;
    int row = blockIdx.x * 8 + w;
    float s = 0.f;
    for (int k = lane; k < H; k += 32) s += Wh[row * H + k] * rh[k];
    for (int o = 16; o; o >>= 1) s += __shfl_xor_sync(0xffffffffu, s, o);
    if (lane == 0) {
        float c = tanhf(s + g_pre[2 * H + row]);
        float z = 1.f / (1.f + expf(-g_pre[row]));
        hn_out[row] = (1.f - z) * c + z * hidden[row];
    }
}

// ---------------- K8: logits = V_w @ hidden_new + V_b (1024 blocks) -------
__global__ __launch_bounds__(256) void k8_logits(const float* __restrict__ Vw,
                                                 const float* __restrict__ Vb,
                                                 const float* __restrict__ hn) {
    __shared__ float hs[H];
    int tid = threadIdx.x;
    hs[tid] = hn[tid];
    __syncthreads();
    int w = tid >> 5, lane = tid & 31;
    int row = blockIdx.x * 8 + w;
    const float4* v4 = reinterpret_cast<const float4*>(Vw + (size_t)row * H);
    const float4* h4 = reinterpret_cast<const float4*>(hs);
    float4 a = v4[lane], b = h4[lane];
    float s = a.x * b.x + a.y * b.y + a.z * b.z + a.w * b.w;
    a = v4[lane + 32]; b = h4[lane + 32];
    s += a.x * b.x + a.y * b.y + a.z * b.z + a.w * b.w;
    for (int o = 16; o; o >>= 1) s += __shfl_xor_sync(0xffffffffu, s, o);
    if (lane == 0) g_logits[row] = s + Vb[row];
}

// ---------------- K9: log_softmax over V (single block) -------------------
__global__ __launch_bounds__(1024) void k9_lsm(float* __restrict__ out) {
    __shared__ float red[32];
    __shared__ float stat;
    int tid = threadIdx.x;
    float v[8];
    float mx = -1e30f;
#pragma unroll
    for (int i = 0; i < 8; i++) { v[i] = g_logits[i * 1024 + tid]; mx = fmaxf(mx, v[i]); }
    for (int o = 16; o; o >>= 1) mx = fmaxf(mx, __shfl_xor_sync(0xffffffffu, mx, o));
    if ((tid & 31) == 0) red[tid >> 5] = mx;
    __syncthreads();
    if (tid == 0) {
        float m = red[0];
        for (int i = 1; i < 32; i++) m = fmaxf(m, red[i]);
        stat = m;
    }
    __syncthreads();
    mx = stat;
    float sum = 0.f;
#pragma unroll
    for (int i = 0; i < 8; i++) sum += expf(v[i] - mx);
    for (int o = 16; o; o >>= 1) sum += __shfl_xor_sync(0xffffffffu, sum, o);
    __syncthreads();
    if ((tid & 31) == 0) red[tid >> 5] = sum;
    __syncthreads();
    if (tid == 0) {
        float t = 0.f;
        for (int i = 0; i < 32; i++) t += red[i];
        stat = t;
    }
    __syncthreads();
    float lse = mx + logf(stat);
#pragma unroll
    for (int i = 0; i < 8; i++) out[i * 1024 + tid] = v[i] - lse;
}

// ---------------- launch ----------------
extern "C" void kernel_launch(void* const* d_in, const int* in_sizes, int n_in,
                              void* d_out, int out_size) {
    const int*   input_tok = (const int*)d_in[0];
    const float* hidden    = (const float*)d_in[1];
    const float* enc       = (const float*)d_in[2];
    const float* emb       = (const float*)d_in[3];
    const float* Uz_w = (const float*)d_in[4],  *Uz_b = (const float*)d_in[5];
    const float* Wz_w = (const float*)d_in[6],  *Wz_b = (const float*)d_in[7];
    const float* Cz_w = (const float*)d_in[8],  *Cz_b = (const float*)d_in[9];
    const float* Ur_w = (const float*)d_in[10], *Ur_b = (const float*)d_in[11];
    const float* Wr_w = (const float*)d_in[12], *Wr_b = (const float*)d_in[13];
    const float* Cr_w = (const float*)d_in[14], *Cr_b = (const float*)d_in[15];
    const float* Uh_w = (const float*)d_in[16], *Uh_b = (const float*)d_in[17];
    const float* Wh_w = (const float*)d_in[18], *Wh_b = (const float*)d_in[19];
    const float* Ch_w = (const float*)d_in[20], *Ch_b = (const float*)d_in[21];
    const float* Ua_w = (const float*)d_in[22], *Ua_b = (const float*)d_in[23];
    const float* Wa_w = (const float*)d_in[24], *Wa_b = (const float*)d_in[25];
    const float* Va_w = (const float*)d_in[26], *Va_b = (const float*)d_in[27];
    const float* V_w  = (const float*)d_in[28], *V_b  = (const float*)d_in[29];
    (void)Va_b; (void)in_sizes; (void)n_in; (void)out_size;

    float* out = (float*)d_out;           // [0:8192) log-probs
    float* hn  = out + VOCAB;             // [8192:8448) hidden_new
    float* aij = out + VOCAB + H;         // [8448:12544) attention weights

    k1_wah<<<32, 256>>>(Wa_w, Wa_b, Ua_b, hidden);
    k2_attn<<<dim3(SEQ / TM, 2), 256>>>(enc, Ua_w, Va_w);
    k3_softmax<<<1, 256>>>(aij);
    k4_ci<<<16, 256>>>(enc, aij);
    k5_cired<<<1, 512>>>();
    k6_gates<<<768, 256>>>(emb, input_tok, hidden,
                           Uz_w, Uz_b, Wz_w, Wz_b, Cz_w, Cz_b,
                           Ur_w, Ur_b, Wr_w, Wr_b, Cr_w, Cr_b,
                           Uh_w, Uh_b, Wh_b, Ch_w, Ch_b);
    k7_combine<<<32, 256>>>(Wh_w, hidden, hn);
    k8_logits<<<VOCAB / 8, 256>>>(V_w, V_b, hn);
    k9_lsm<<<1, 1024>>>(out);
}

// round 8
// speedup vs baseline: 1.0908x; 1.0908x over previous
#include <cuda_runtime.h>
#include <math.h>

#define H 256
#define H2 512
#define VOCAB 8192
#define SEQ 4096

#define CIB 128            // k4 blocks
#define CIR (SEQ / CIB)    // 32 s-rows per block

// ---------------- device scratch (no allocations allowed) ----------------
__device__ float g_wah[H];           // Wa@h + Wa_b + Ua_b
__device__ float g_Eij[2 * SEQ];     // attention scores, partial over two n-halves
__device__ float g_CiP[CIB][H2];     // Ci partials (deterministic reduction)
__device__ float g_Ci[H2];           // context vector
__device__ float g_pre[3 * H];       // gate pre-activations: z, r, h-partial
__device__ float g_logits[VOCAB];

// ---------------- f32x2 packed-math helpers (sm_100+) ----------------
static __device__ __forceinline__ unsigned long long pack2(float lo, float hi) {
    unsigned long long r;
    asm("mov.b64 %0, {%1,%2};" : "=l"(r) : "f"(lo), "f"(hi));
    return r;
}
static __device__ __forceinline__ void unpack2(unsigned long long v, float& lo, float& hi) {
    asm("mov.b64 {%0,%1}, %2;" : "=f"(lo), "=f"(hi) : "l"(v));
}
static __device__ __forceinline__ void fma2(unsigned long long& d,
                                            unsigned long long a,
                                            unsigned long long b) {
    asm("fma.rn.f32x2 %0, %1, %2, %0;" : "+l"(d) : "l"(a), "l"(b));
}

// ---------------- K1: wa_h[n] = Wa@hidden + Wa_b + Ua_b ----------------
__global__ void k1_wah(const float* __restrict__ Wa_w, const float* __restrict__ Wa_b,
                       const float* __restrict__ Ua_b, const float* __restrict__ hidden) {
    int w = threadIdx.x >> 5, lane = threadIdx.x & 31;
    int row = blockIdx.x * 8 + w;
    float s = 0.f;
    for (int k = lane; k < H; k += 32) s += Wa_w[row * H + k] * hidden[k];
    for (int o = 16; o; o >>= 1) s += __shfl_xor_sync(0xffffffffu, s, o);
    if (lane == 0) g_wah[row] = s + Wa_b[row] + Ua_b[row];
}

// ---------------- K2: fused attention-score GEMM ----------------
// C[s,n] = enc[s,:] . Ua_w[n,:];  Eij_part[by][s] = sum_n Va[n]*tanh(C+wa_h[n])
#define TM 64
#define TN 128
#define KT 32

__global__ __launch_bounds__(256) void k2_attn(const float* __restrict__ enc,
                                               const float* __restrict__ Ua_w,
                                               const float* __restrict__ Va_w) {
    __shared__ __align__(16) unsigned long long As2[TM][KT + 1]; // (a,a) packed
    __shared__ __align__(16) float Bs[KT][TN];
    __shared__ float wah_s[TN];
    __shared__ float vas[TN];

    int tid = threadIdx.x;
    int s0 = blockIdx.x * TM;
    int n0 = blockIdx.y * TN;
    if (tid < TN) { wah_s[tid] = g_wah[n0 + tid]; vas[tid] = Va_w[n0 + tid]; }

    int tidx = tid & 15;   // n-group (16)
    int tidy = tid >> 4;   // m-group (16)

    unsigned long long acc[4][4];
#pragma unroll
    for (int i = 0; i < 4; i++)
#pragma unroll
        for (int j = 0; j < 4; j++) acc[i][j] = 0ull;

    int ar = tid >> 2, aq = tid & 3;   // A loader: row 0..63, quad 0..3
    int bn = tid >> 1, bh = tid & 1;   // B loader: row 0..127, half 0..1
    const float4* Abase = reinterpret_cast<const float4*>(enc + (size_t)(s0 + ar) * H2);
    const float4* Bbase = reinterpret_cast<const float4*>(Ua_w + (size_t)(n0 + bn) * H2);

    float4 a0 = Abase[aq], a1 = Abase[aq + 4];
    float4 b0 = Bbase[bh * 4 + 0], b1 = Bbase[bh * 4 + 1];
    float4 b2 = Bbase[bh * 4 + 2], b3 = Bbase[bh * 4 + 3];

    const int NIT = H2 / KT;
    for (int it = 0; it < NIT; ++it) {
        // stage registers -> smem
        As2[ar][4 * aq + 0]  = pack2(a0.x, a0.x);
        As2[ar][4 * aq + 1]  = pack2(a0.y, a0.y);
        As2[ar][4 * aq + 2]  = pack2(a0.z, a0.z);
        As2[ar][4 * aq + 3]  = pack2(a0.w, a0.w);
        As2[ar][4 * aq + 16] = pack2(a1.x, a1.x);
        As2[ar][4 * aq + 17] = pack2(a1.y, a1.y);
        As2[ar][4 * aq + 18] = pack2(a1.z, a1.z);
        As2[ar][4 * aq + 19] = pack2(a1.w, a1.w);
        int cb = bh * 16;
        Bs[cb + 0][bn] = b0.x;  Bs[cb + 1][bn] = b0.y;
        Bs[cb + 2][bn] = b0.z;  Bs[cb + 3][bn] = b0.w;
        Bs[cb + 4][bn] = b1.x;  Bs[cb + 5][bn] = b1.y;
        Bs[cb + 6][bn] = b1.z;  Bs[cb + 7][bn] = b1.w;
        Bs[cb + 8][bn] = b2.x;  Bs[cb + 9][bn] = b2.y;
        Bs[cb + 10][bn] = b2.z; Bs[cb + 11][bn] = b2.w;
        Bs[cb + 12][bn] = b3.x; Bs[cb + 13][bn] = b3.y;
        Bs[cb + 14][bn] = b3.z; Bs[cb + 15][bn] = b3.w;
        __syncthreads();

        if (it + 1 < NIT) {  // prefetch next tile (hides GMEM latency behind FMAs)
            int o = (it + 1) * 8;
            a0 = Abase[o + aq];          a1 = Abase[o + aq + 4];
            b0 = Bbase[o + bh * 4 + 0];  b1 = Bbase[o + bh * 4 + 1];
            b2 = Bbase[o + bh * 4 + 2];  b3 = Bbase[o + bh * 4 + 3];
        }

#pragma unroll 8
        for (int k = 0; k < KT; k++) {
            unsigned long long a[4], b[4];
#pragma unroll
            for (int i = 0; i < 4; i++) a[i] = As2[tidy * 4 + i][k];
#pragma unroll
            for (int j = 0; j < 4; j++)
                b[j] = *reinterpret_cast<const unsigned long long*>(&Bs[k][tidx * 2 + 32 * j]);
#pragma unroll
            for (int i = 0; i < 4; i++)
#pragma unroll
                for (int j = 0; j < 4; j++) fma2(acc[i][j], a[i], b[j]);
        }
        __syncthreads();
    }

    // fused epilogue: tanh + Va-dot, reduce across the 16 n-thread groups
#pragma unroll
    for (int i = 0; i < 4; i++) {
        float p = 0.f;
#pragma unroll
        for (int j = 0; j < 4; j++) {
            float c0, c1;
            unpack2(acc[i][j], c0, c1);
            int nl = tidx * 2 + 32 * j;
            float e0 = tanhf(c0 + wah_s[nl]);
            float e1 = tanhf(c1 + wah_s[nl + 1]);
            p += e0 * vas[nl] + e1 * vas[nl + 1];
        }
        for (int o = 1; o < 16; o <<= 1) p += __shfl_xor_sync(0xffffffffu, p, o, 16);
        if (tidx == 0) g_Eij[blockIdx.y * SEQ + s0 + tidy * 4 + i] = p;
    }
}

// ---------------- K3: softmax over S (single block) ----------------------
__global__ __launch_bounds__(256) void k3_softmax(float* __restrict__ aij) {
    __shared__ float red[8];
    __shared__ float stat;
    int tid = threadIdx.x;

    float e[16];
    float mx = -1e30f;
#pragma unroll
    for (int i = 0; i < 16; i++) {
        e[i] = g_Eij[i * 256 + tid] + g_Eij[SEQ + i * 256 + tid];
        mx = fmaxf(mx, e[i]);
    }
    for (int o = 16; o; o >>= 1) mx = fmaxf(mx, __shfl_xor_sync(0xffffffffu, mx, o));
    if ((tid & 31) == 0) red[tid >> 5] = mx;
    __syncthreads();
    if (tid == 0) {
        float m = red[0];
        for (int i = 1; i < 8; i++) m = fmaxf(m, red[i]);
        stat = m;
    }
    __syncthreads();
    mx = stat;

    float sum = 0.f;
#pragma unroll
    for (int i = 0; i < 16; i++) { e[i] = expf(e[i] - mx); sum += e[i]; }
    for (int o = 16; o; o >>= 1) sum += __shfl_xor_sync(0xffffffffu, sum, o);
    __syncthreads();
    if ((tid & 31) == 0) red[tid >> 5] = sum;
    __syncthreads();
    if (tid == 0) {
        float t = 0.f;
        for (int i = 0; i < 8; i++) t += red[i];
        stat = t;
    }
    __syncthreads();
    float inv = 1.f / stat;
#pragma unroll
    for (int i = 0; i < 16; i++) aij[i * 256 + tid] = e[i] * inv;
}

// ---------------- K4: Ci partials (128 blocks x 512 thr, deterministic) ---
// Each block handles 32 s-rows; each thread owns one of the 512 columns.
// Fully unrolled -> 32 independent LDGs in flight per thread (high MLP).
__global__ __launch_bounds__(512) void k4_ci(const float* __restrict__ enc,
                                             const float* __restrict__ aij) {
    int b = blockIdx.x, tid = threadIdx.x;
    const float* ep = enc + (size_t)b * CIR * H2 + tid;
    const float* ap = aij + b * CIR;
    float w[CIR];
#pragma unroll
    for (int s = 0; s < CIR; s++) w[s] = __ldg(ap + s);
    float acc = 0.f;
#pragma unroll
    for (int s = 0; s < CIR; s++) acc += w[s] * __ldg(ep + (size_t)s * H2);
    g_CiP[b][tid] = acc;
}

// ---------------- K5: reduce Ci partials (fixed order) --------------------
__global__ __launch_bounds__(512) void k5_cired() {
    int tid = threadIdx.x;
    float s = 0.f;
#pragma unroll 16
    for (int b = 0; b < CIB; b++) s += g_CiP[b][tid];
    g_Ci[tid] = s;
}

// ---------------- K6: gate pre-activations (768 blocks, block-per-row) ---
__global__ __launch_bounds__(256) void k6_gates(
    const float* __restrict__ emb, const int* __restrict__ tokp,
    const float* __restrict__ hidden,
    const float* __restrict__ Uz, const float* __restrict__ Uzb,
    const float* __restrict__ Wz, const float* __restrict__ Wzb,
    const float* __restrict__ Cz, const float* __restrict__ Czb,
    const float* __restrict__ Ur, const float* __restrict__ Urb,
    const float* __restrict__ Wr, const float* __restrict__ Wrb,
    const float* __restrict__ Cr, const float* __restrict__ Crb,
    const float* __restrict__ Uh, const float* __restrict__ Uhb,
    const float* __restrict__ Whb,
    const float* __restrict__ Ch, const float* __restrict__ Chb) {
    __shared__ float red[8];
    int g = blockIdx.x >> 8, row = blockIdx.x & 255, tid = threadIdx.x;
    const float* U = (g == 0) ? Uz : (g == 1) ? Ur : Uh;
    int tok = __ldg(tokp);
    const float4* y4 = reinterpret_cast<const float4*>(emb + (size_t)tok * VOCAB);
    const float4* u4 = reinterpret_cast<const float4*>(U + (size_t)row * VOCAB);

    float s = 0.f;
#pragma unroll 4
    for (int i = tid; i < VOCAB / 4; i += 256) {
        float4 u = u4[i], y = y4[i];
        s += u.x * y.x + u.y * y.y + u.z * y.z + u.w * y.w;
    }
    if (g < 2) {
        const float* W = (g == 0) ? Wz : Wr;
        s += W[row * H + tid] * hidden[tid];
    }
    const float* C = (g == 0) ? Cz : (g == 1) ? Cr : Ch;
    s += C[row * H2 + tid] * g_Ci[tid] + C[row * H2 + tid + 256] * g_Ci[tid + 256];

    for (int o = 16; o; o >>= 1) s += __shfl_xor_sync(0xffffffffu, s, o);
    if ((tid & 31) == 0) red[tid >> 5] = s;
    __syncthreads();
    if (tid == 0) {
        float t = 0.f;
        for (int i = 0; i < 8; i++) t += red[i];
        float bias = (g == 0) ? (Uzb[row] + Wzb[row] + Czb[row])
                   : (g == 1) ? (Urb[row] + Wrb[row] + Crb[row])
                              : (Uhb[row] + Whb[row] + Chb[row]);
        g_pre[g * H + row] = t + bias;
    }
}

// ---------------- K7: finish GRU -> hidden_new (32 blocks) ----------------
__global__ __launch_bounds__(256) void k7_combine(const float* __restrict__ Wh,
                                                  const float* __restrict__ hidden,
                                                  float* __restrict__ hn_out) {
    __shared__ float rh[H];
    int tid = threadIdx.x;
    float rr = 1.f / (1.f + expf(-g_pre[H + tid]));
    rh[tid] = rr * hidden[tid];
    __syncthreads();
    int w = tid >> 5, lane = tid & 31;
    int row = blockIdx.x * 8 + w;
    float s = 0.f;
    for (int k = lane; k < H; k += 32) s += Wh[row * H + k] * rh[k];
    for (int o = 16; o; o >>= 1) s += __shfl_xor_sync(0xffffffffu, s, o);
    if (lane == 0) {
        float c = tanhf(s + g_pre[2 * H + row]);
        float z = 1.f / (1.f + expf(-g_pre[row]));
        hn_out[row] = (1.f - z) * c + z * hidden[row];
    }
}

// ---------------- K8: logits = V_w @ hidden_new + V_b (1024 blocks) -------
__global__ __launch_bounds__(256) void k8_logits(const float* __restrict__ Vw,
                                                 const float* __restrict__ Vb,
                                                 const float* __restrict__ hn) {
    __shared__ float hs[H];
    int tid = threadIdx.x;
    hs[tid] = hn[tid];
    __syncthreads();
    int w = tid >> 5, lane = tid & 31;
    int row = blockIdx.x * 8 + w;
    const float4* v4 = reinterpret_cast<const float4*>(Vw + (size_t)row * H);
    const float4* h4 = reinterpret_cast<const float4*>(hs);
    float4 a = v4[lane], b = h4[lane];
    float s = a.x * b.x + a.y * b.y + a.z * b.z + a.w * b.w;
    a = v4[lane + 32]; b = h4[lane + 32];
    s += a.x * b.x + a.y * b.y + a.z * b.z + a.w * b.w;
    for (int o = 16; o; o >>= 1) s += __shfl_xor_sync(0xffffffffu, s, o);
    if (lane == 0) g_logits[row] = s + Vb[row];
}

// ---------------- K9: log_softmax over V (single block) -------------------
__global__ __launch_bounds__(1024) void k9_lsm(float* __restrict__ out) {
    __shared__ float red[32];
    __shared__ float stat;
    int tid = threadIdx.x;
    float v[8];
    float mx = -1e30f;
#pragma unroll
    for (int i = 0; i < 8; i++) { v[i] = g_logits[i * 1024 + tid]; mx = fmaxf(mx, v[i]); }
    for (int o = 16; o; o >>= 1) mx = fmaxf(mx, __shfl_xor_sync(0xffffffffu, mx, o));
    if ((tid & 31) == 0) red[tid >> 5] = mx;
    __syncthreads();
    if (tid == 0) {
        float m = red[0];
        for (int i = 1; i < 32; i++) m = fmaxf(m, red[i]);
        stat = m;
    }
    __syncthreads();
    mx = stat;
    float sum = 0.f;
#pragma unroll
    for (int i = 0; i < 8; i++) sum += expf(v[i] - mx);
    for (int o = 16; o; o >>= 1) sum += __shfl_xor_sync(0xffffffffu, sum, o);
    __syncthreads();
    if ((tid & 31) == 0) red[tid >> 5] = sum;
    __syncthreads();
    if (tid == 0) {
        float t = 0.f;
        for (int i = 0; i < 32; i++) t += red[i];
        stat = t;
    }
    __syncthreads();
    float lse = mx + logf(stat);
#pragma unroll
    for (int i = 0; i < 8; i++) out[i * 1024 + tid] = v[i] - lse;
}

// ---------------- launch ----------------
extern "C" void kernel_launch(void* const* d_in, const int* in_sizes, int n_in,
                              void* d_out, int out_size) {
    const int*   input_tok = (const int*)d_in[0];
    const float* hidden    = (const float*)d_in[1];
    const float* enc       = (const float*)d_in[2];
    const float* emb       = (const float*)d_in[3];
    const float* Uz_w = (const float*)d_in[4],  *Uz_b = (const float*)d_in[5];
    const float* Wz_w = (const float*)d_in[6],  *Wz_b = (const float*)d_in[7];
    const float* Cz_w = (const float*)d_in[8],  *Cz_b = (const float*)d_in[9];
    const float* Ur_w = (const float*)d_in[10], *Ur_b = (const float*)d_in[11];
    const float* Wr_w = (const float*)d_in[12], *Wr_b = (const float*)d_in[13];
    const float* Cr_w = (const float*)d_in[14], *Cr_b = (const float*)d_in[15];
    const float* Uh_w = (const float*)d_in[16], *Uh_b = (const float*)d_in[17];
    const float* Wh_w = (const float*)d_in[18], *Wh_b = (const float*)d_in[19];
    const float* Ch_w = (const float*)d_in[20], *Ch_b = (const float*)d_in[21];
    const float* Ua_w = (const float*)d_in[22], *Ua_b = (const float*)d_in[23];
    const float* Wa_w = (const float*)d_in[24], *Wa_b = (const float*)d_in[25];
    const float* Va_w = (const float*)d_in[26], *Va_b = (const float*)d_in[27];
    const float* V_w  = (const float*)d_in[28], *V_b  = (const float*)d_in[29];
    (void)Va_b; (void)in_sizes; (void)n_in; (void)out_size;

    float* out = (float*)d_out;           // [0:8192) log-probs
    float* hn  = out + VOCAB;             // [8192:8448) hidden_new
    float* aij = out + VOCAB + H;         // [8448:12544) attention weights

    k1_wah<<<32, 256>>>(Wa_w, Wa_b, Ua_b, hidden);
    k2_attn<<<dim3(SEQ / TM, 2), 256>>>(enc, Ua_w, Va_w);
    k3_softmax<<<1, 256>>>(aij);
    k4_ci<<<CIB, 512>>>(enc, aij);
    k5_cired<<<1, 512>>>();
    k6_gates<<<768, 256>>>(emb, input_tok, hidden,
                           Uz_w, Uz_b, Wz_w, Wz_b, Cz_w, Cz_b,
                           Ur_w, Ur_b, Wr_w, Wr_b, Cr_w, Cr_b,
                           Uh_w, Uh_b, Wh_b, Ch_w, Ch_b);
    k7_combine<<<32, 256>>>(Wh_w, hidden, hn);
    k8_logits<<<VOCAB / 8, 256>>>(V_w, V_b, hn);
    k9_lsm<<<1, 1024>>>(out);
}